// round 1
// baseline (speedup 1.0000x reference)
#include <cuda_runtime.h>
#include <cuda_bf16.h>

// VQ codebook quantization:
//   scores[n,k] = z[n]·e[k] - 0.5*||e[k]||^2 ; idx[n] = argmax_k ; out = e[idx]
// N = 65536, D = 64, K = 1024.
// Output: [N*D floats quantized][N floats indices] (indices written only if
// out_size covers them).

#define DDIM 64
#define TM 128
#define TK 128
#define KMAX 8192

__device__ float g_cnorm[KMAX];

__global__ void cnorm_kernel(const float* __restrict__ emb, int K) {
    int k = blockIdx.x * blockDim.x + threadIdx.x;
    if (k < K) {
        const float4* e4 = reinterpret_cast<const float4*>(emb + (size_t)k * DDIM);
        float s = 0.f;
#pragma unroll
        for (int i = 0; i < DDIM / 4; i++) {
            float4 v = e4[i];
            s += v.x * v.x + v.y * v.y + v.z * v.z + v.w * v.w;
        }
        g_cnorm[k] = 0.5f * s;
    }
}

__global__ __launch_bounds__(256, 2)
void vq_kernel(const float* __restrict__ z, const float* __restrict__ emb,
               float* __restrict__ out, int N, int K, int write_idx) {
    extern __shared__ float smem[];
    float* zs = smem;                 // [DDIM][TM]  32 KB, transposed
    float* es = smem + DDIM * TM;     // [DDIM][TK]  32 KB, transposed
    int* finalIdx = (int*)(smem + 2 * DDIM * TM);  // [TM]

    const int tid = threadIdx.x;
    const int tx = tid & 15;   // code dim (16)
    const int ty = tid >> 4;   // row dim  (16)
    const int rowBase = blockIdx.x * TM;

    // ---- load Z tile, transposed into zs[d][row] ----
#pragma unroll
    for (int t = 0; t < (TM * DDIM / 4) / 256; t++) {   // 8 iters
        int idx = tid + t * 256;
        int row = idx >> 4;        // 0..127
        int d4  = idx & 15;        // 0..15
        float4 v = reinterpret_cast<const float4*>(z + (size_t)(rowBase + row) * DDIM)[d4];
        zs[(d4 * 4 + 0) * TM + row] = v.x;
        zs[(d4 * 4 + 1) * TM + row] = v.y;
        zs[(d4 * 4 + 2) * TM + row] = v.z;
        zs[(d4 * 4 + 3) * TM + row] = v.w;
    }

    float best[8];
    int bidx[8];
#pragma unroll
    for (int i = 0; i < 8; i++) { best[i] = -3.402823e38f; bidx[i] = 0; }

    for (int kc = 0; kc < K; kc += TK) {
        __syncthreads();  // es reuse guard (also covers zs on first iter)
        // ---- load E chunk, transposed into es[d][code] ----
#pragma unroll
        for (int t = 0; t < (TK * DDIM / 4) / 256; t++) {  // 8 iters
            int idx = tid + t * 256;
            int code = idx >> 4;
            int d4 = idx & 15;
            float4 v = reinterpret_cast<const float4*>(emb + (size_t)(kc + code) * DDIM)[d4];
            es[(d4 * 4 + 0) * TK + code] = v.x;
            es[(d4 * 4 + 1) * TK + code] = v.y;
            es[(d4 * 4 + 2) * TK + code] = v.z;
            es[(d4 * 4 + 3) * TK + code] = v.w;
        }
        __syncthreads();

        float acc[8][8];
#pragma unroll
        for (int i = 0; i < 8; i++)
#pragma unroll
            for (int j = 0; j < 8; j++) acc[i][j] = 0.f;

        const float4* zs4 = reinterpret_cast<const float4*>(zs);
        const float4* es4 = reinterpret_cast<const float4*>(es);
#pragma unroll 8
        for (int d = 0; d < DDIM; d++) {
            float4 zA = zs4[d * (TM / 4) + ty * 2 + 0];
            float4 zB = zs4[d * (TM / 4) + ty * 2 + 1];
            float4 eA = es4[d * (TK / 4) + tx * 2 + 0];
            float4 eB = es4[d * (TK / 4) + tx * 2 + 1];
            float zr[8] = {zA.x, zA.y, zA.z, zA.w, zB.x, zB.y, zB.z, zB.w};
            float er[8] = {eA.x, eA.y, eA.z, eA.w, eB.x, eB.y, eB.z, eB.w};
#pragma unroll
            for (int i = 0; i < 8; i++)
#pragma unroll
                for (int j = 0; j < 8; j++)
                    acc[i][j] = fmaf(zr[i], er[j], acc[i][j]);
        }

        // ---- fold scores into running argmax (codes ascend -> first-min tiebreak) ----
#pragma unroll
        for (int j = 0; j < 8; j++) {
            int code = kc + tx * 8 + j;
            float cn = g_cnorm[code];
#pragma unroll
            for (int i = 0; i < 8; i++) {
                float s = acc[i][j] - cn;
                if (s > best[i]) { best[i] = s; bidx[i] = code; }
            }
        }
    }

    __syncthreads();
    // ---- cross-thread reduction over the 16 code-columns, reusing es ----
    float* rval = es;                  // [TM][16]
    int*   ridx = (int*)(es + TM * 16);  // [TM][16]
#pragma unroll
    for (int i = 0; i < 8; i++) {
        rval[(ty * 8 + i) * 16 + tx] = best[i];
        ridx[(ty * 8 + i) * 16 + tx] = bidx[i];
    }
    __syncthreads();
    if (tid < TM) {
        float b = rval[tid * 16 + 0];
        int bi = ridx[tid * 16 + 0];
#pragma unroll
        for (int t = 1; t < 16; t++) {
            float v = rval[tid * 16 + t];
            int vi = ridx[tid * 16 + t];
            // ascending tx == ascending code blocks; strict > keeps first occurrence
            if (v > b || (v == b && vi < bi)) { b = v; bi = vi; }
        }
        finalIdx[tid] = bi;
        if (write_idx)
            out[(size_t)N * DDIM + rowBase + tid] = (float)bi;
    }
    __syncthreads();

    // ---- gather quantized rows from embeddings (E chunk is L2-hot) ----
#pragma unroll
    for (int t = 0; t < (TM * DDIM / 4) / 256; t++) {
        int idx = tid + t * 256;
        int row = idx >> 4;
        int d4 = idx & 15;
        float4 v = reinterpret_cast<const float4*>(emb + (size_t)finalIdx[row] * DDIM)[d4];
        reinterpret_cast<float4*>(out + (size_t)(rowBase + row) * DDIM)[d4] = v;
    }
}

extern "C" void kernel_launch(void* const* d_in, const int* in_sizes, int n_in,
                              void* d_out, int out_size) {
    const float* z = (const float*)d_in[0];
    const float* emb = (const float*)d_in[1];
    // Disambiguate by size: z is the big one.
    if (n_in >= 2 && in_sizes[1] > in_sizes[0]) {
        const float* t = z; z = emb; emb = t;
        // sizes swap handled below via locals
    }
    int zsize = in_sizes[0], esize = in_sizes[1];
    if (esize > zsize) { int t = zsize; zsize = esize; esize = t; }

    int N = zsize / DDIM;    // 65536
    int K = esize / DDIM;    // 1024
    float* out = (float*)d_out;
    int write_idx = (out_size >= N * DDIM + N) ? 1 : 0;

    cnorm_kernel<<<(K + 255) / 256, 256>>>(emb, K);

    int smem_bytes = (2 * DDIM * TM + TM) * (int)sizeof(float);  // 66 KB
    static int attr_set = 0;
    if (!attr_set) {
        cudaFuncSetAttribute(vq_kernel, cudaFuncAttributeMaxDynamicSharedMemorySize,
                             smem_bytes);
        attr_set = 1;
    }
    vq_kernel<<<N / TM, 256, smem_bytes>>>(z, emb, out, N, K, write_idx);
}